// round 7
// baseline (speedup 1.0000x reference)
#include <cuda_runtime.h>
#include <cstdint>
#include <cstddef>

#define NN   8192
#define FIN  256
#define FOUT 128
#define ALPHA_SLOPE 0.2f

#define PB_STRIDE 72                   // P tile row stride (floats), 32 rows
#define BB_KT     1024                 // B per-k-tile stride (contiguous)
#define P_FLOATS  (32 * PB_STRIDE)     // 2304
#define B_FLOATS  (8 * BB_KT)          // 8192
#define STAGE_FLOATS (P_FLOATS + B_FLOATS)   // 10496

// ---------------- scratch (device globals: no allocation allowed) ------------
// g_WhB: Wh pre-staged in MMA-B layout per 64-row j-tile (8192 floats each):
//   addr = tile*8192 + kt*1024 + f*8 + (kl&3)*2 + (kl>>2),  row = tile*64+kt*8+kl
__device__ float g_WhB[(size_t)NN * FOUT];
__device__ float g_f1[NN];
__device__ float g_f2[NN];

// ---------------- helpers ----------------------------------------------------
__device__ __forceinline__ float to_tf32(float x) {
    uint32_t u;
    asm("cvt.rna.tf32.f32 %0, %1;" : "=r"(u) : "f"(x));
    return __uint_as_float(u);
}

__device__ __forceinline__ void mma_tf32(float* c,
                                         uint32_t a0, uint32_t a1, uint32_t a2, uint32_t a3,
                                         uint32_t b0, uint32_t b1) {
    asm volatile(
        "mma.sync.aligned.m16n8k8.row.col.f32.tf32.tf32.f32 "
        "{%0,%1,%2,%3}, {%4,%5,%6,%7}, {%8,%9}, {%0,%1,%2,%3};\n"
        : "+f"(c[0]), "+f"(c[1]), "+f"(c[2]), "+f"(c[3])
        : "r"(a0), "r"(a1), "r"(a2), "r"(a3), "r"(b0), "r"(b1));
}

__device__ __forceinline__ float lrelu_exp(float s) {
    s = fmaxf(s, ALPHA_SLOPE * s);
    return __expf(s);
}

__device__ __forceinline__ void cp_async16(uint32_t smem_dst, const void* gsrc) {
    asm volatile("cp.async.cg.shared.global [%0], [%1], 16;\n"
                 :: "r"(smem_dst), "l"(gsrc));
}
__device__ __forceinline__ void cp_async_commit() {
    asm volatile("cp.async.commit_group;\n");
}
__device__ __forceinline__ void cp_async_wait0() {
    asm volatile("cp.async.wait_group 0;\n");
}

// ---------------- Kernel A: Wh = h@W (stored in B layout), f1, f2 ------------
__global__ void __launch_bounds__(256) wh_kernel(const float* __restrict__ h,
                                                 const float* __restrict__ W,
                                                 const float* __restrict__ a) {
    __shared__ float hs[64][64];
    __shared__ float Ws[64][FOUT];

    const int t  = threadIdx.x;
    const int i0 = blockIdx.x * 64;
    const int tf = t & 31;      // 4 output cols tf*4..+3
    const int ti = t >> 5;      // 8 output rows ti*8..+7  (kt = ti, kl = r)

    float acc[8][4];
#pragma unroll
    for (int r = 0; r < 8; ++r)
#pragma unroll
        for (int c = 0; c < 4; ++c) acc[r][c] = 0.f;

    for (int kc = 0; kc < 4; ++kc) {
        __syncthreads();
#pragma unroll
        for (int idx = t; idx < 1024; idx += 256) {
            int row = idx >> 4, c = idx & 15;
            *(float4*)&hs[row][c * 4] =
                *(const float4*)&h[(size_t)(i0 + row) * FIN + kc * 64 + c * 4];
        }
#pragma unroll
        for (int idx = t; idx < 2048; idx += 256) {
            int row = idx >> 5, c = idx & 31;
            *(float4*)&Ws[row][c * 4] =
                *(const float4*)&W[(size_t)(kc * 64 + row) * FOUT + c * 4];
        }
        __syncthreads();
#pragma unroll 8
        for (int k = 0; k < 64; ++k) {
            float4 wv = *(float4*)&Ws[k][tf * 4];
#pragma unroll
            for (int r = 0; r < 8; ++r) {
                float hv = hs[ti * 8 + r][k];
                acc[r][0] += hv * wv.x;
                acc[r][1] += hv * wv.y;
                acc[r][2] += hv * wv.z;
                acc[r][3] += hv * wv.w;
            }
        }
    }

    float4 a1v = *(const float4*)&a[tf * 4];
    float4 a2v = *(const float4*)&a[FOUT + tf * 4];
#pragma unroll
    for (int r = 0; r < 8; ++r) {
        float v1 = acc[r][0] * a1v.x + acc[r][1] * a1v.y + acc[r][2] * a1v.z + acc[r][3] * a1v.w;
        float v2 = acc[r][0] * a2v.x + acc[r][1] * a2v.y + acc[r][2] * a2v.z + acc[r][3] * a2v.w;
#pragma unroll
        for (int off = 16; off > 0; off >>= 1) {
            v1 += __shfl_xor_sync(0xffffffffu, v1, off);
            v2 += __shfl_xor_sync(0xffffffffu, v2, off);
        }
        if (tf == 0) {
            g_f1[i0 + ti * 8 + r] = v1;
            g_f2[i0 + ti * 8 + r] = v2;
        }
    }

    // store into B-staged layout: slot (kl&3)*2 + (kl>>2); rows r and r+4 pair
    float* base = &g_WhB[(size_t)blockIdx.x * 8192 + ti * 1024];
#pragma unroll
    for (int r = 0; r < 4; ++r) {
#pragma unroll
        for (int c = 0; c < 4; ++c) {
            float2 v;
            v.x = to_tf32(acc[r][c]);       // kl = r     -> slot 2r
            v.y = to_tf32(acc[r + 4][c]);   // kl = r + 4 -> slot 2r+1
            *(float2*)&base[(tf * 4 + c) * 8 + r * 2] = v;
        }
    }
}

// ---------------- Kernel C: fused masked-softmax attention -------------------
// grid 256, block 256 (8 warps, 2 CTAs/SM). Block tile 32(i) x 128(f).
// Warp grid: wf(N,4) x wk(K,2); warp tile 32x32, k-split 2.
// P stored column-permuted so A-fragments load as LDS.64.
__global__ void __launch_bounds__(256, 2) gat_kernel(const int* __restrict__ adj,
                                                     float* __restrict__ out) {
    extern __shared__ float smem[];
    float* Pst[2];
    float* Bst[2];
    Pst[0] = smem;
    Bst[0] = smem + P_FLOATS;
    Pst[1] = smem + STAGE_FLOATS;
    Bst[1] = smem + STAGE_FLOATS + P_FLOATS;
    float* Ssh = smem + 2 * STAGE_FLOATS;   // 32 floats

    const int t    = threadIdx.x;
    const int lane = t & 31;
    const int wid  = t >> 5;
    const int i0   = blockIdx.x * 32;

    const int ii = t >> 3;            // P producer row (0..31)
    const int c8 = t & 7;             // P producer 8-col chunk

    const int wf = wid >> 1;          // 0..3 (N)
    const int wk = wid & 1;           // 0..1 (K split)
    const int l4 = lane >> 2;
    const int lm = lane & 3;

    const float f1i = g_f1[i0 + ii];
    float sacc = 0.f;

    float fragC[2][4][4];
#pragma unroll
    for (int mt = 0; mt < 2; ++mt)
#pragma unroll
        for (int nt = 0; nt < 4; ++nt)
#pragma unroll
            for (int c = 0; c < 4; ++c) fragC[mt][nt][c] = 0.f;

    // invariant addresses
    const int* adj_base = adj + (size_t)(i0 + ii) * NN + c8 * 8;
    const float* whb_base = g_WhB + (size_t)t * 32;          // cp.async src
    uint32_t bdst[2];
    bdst[0] = (uint32_t)__cvta_generic_to_shared(Bst[0]) + t * 128;  // 32 floats
    bdst[1] = (uint32_t)__cvta_generic_to_shared(Bst[1]) + t * 128;
    float* pdst[2];
    pdst[0] = &Pst[0][ii * PB_STRIDE + c8 * 8];
    pdst[1] = &Pst[1][ii * PB_STRIDE + c8 * 8];

    int4   adjA, adjB;
    float4 f2a, f2b;

#define PREFETCH(J0)                                                   \
    do {                                                               \
        const int _j0 = (J0);                                          \
        adjA = *(const int4*)(adj_base + _j0);                         \
        adjB = *(const int4*)(adj_base + _j0 + 4);                     \
        f2a  = *(const float4*)&g_f2[_j0 + c8 * 8];                    \
        f2b  = *(const float4*)&g_f2[_j0 + c8 * 8 + 4];                \
    } while (0)

#define CPASYNC_B(JT, ST)                                              \
    do {                                                               \
        const float* src = whb_base + (size_t)(JT) * 8192;             \
        uint32_t dst = bdst[ST];                                       \
        cp_async16(dst,        src);                                   \
        cp_async16(dst + 16,   src + 4);                               \
        cp_async16(dst + 32,   src + 8);                               \
        cp_async16(dst + 48,   src + 12);                              \
        cp_async16(dst + 64,   src + 16);                              \
        cp_async16(dst + 80,   src + 20);                              \
        cp_async16(dst + 96,   src + 24);                              \
        cp_async16(dst + 112,  src + 28);                              \
        cp_async_commit();                                             \
    } while (0)

// P written permuted: col q (0..7) -> slot (q&3)*2 + (q>>2)
// so slots = [c0,c4,c1,c5,c2,c6,c3,c7]; A-frag (col lm, lm+4) is one float2.
#define STORE_P(ST)                                                    \
    do {                                                               \
        float4 pva, pvb;                                               \
        pva.x = (adjA.x > 0) ? to_tf32(lrelu_exp(f1i + f2a.x)) : 0.f;  \
        pva.y = (adjA.y > 0) ? to_tf32(lrelu_exp(f1i + f2a.y)) : 0.f;  \
        pva.z = (adjA.z > 0) ? to_tf32(lrelu_exp(f1i + f2a.z)) : 0.f;  \
        pva.w = (adjA.w > 0) ? to_tf32(lrelu_exp(f1i + f2a.w)) : 0.f;  \
        pvb.x = (adjB.x > 0) ? to_tf32(lrelu_exp(f1i + f2b.x)) : 0.f;  \
        pvb.y = (adjB.y > 0) ? to_tf32(lrelu_exp(f1i + f2b.y)) : 0.f;  \
        pvb.z = (adjB.z > 0) ? to_tf32(lrelu_exp(f1i + f2b.z)) : 0.f;  \
        pvb.w = (adjB.w > 0) ? to_tf32(lrelu_exp(f1i + f2b.w)) : 0.f;  \
        float4 q0 = make_float4(pva.x, pvb.x, pva.y, pvb.y);           \
        float4 q1 = make_float4(pva.z, pvb.z, pva.w, pvb.w);           \
        *(float4*)(pdst[ST])     = q0;                                 \
        *(float4*)(pdst[ST] + 4) = q1;                                 \
        sacc += pva.x + pva.y + pva.z + pva.w                          \
              + pvb.x + pvb.y + pvb.z + pvb.w;                         \
    } while (0)

    // prologue: fill stage 0
    CPASYNC_B(0, 0);
    PREFETCH(0);
    STORE_P(0);
    cp_async_wait0();
    __syncthreads();

#pragma unroll 1
    for (int jt = 0; jt < NN / 64; ++jt) {
        const int cur = jt & 1;
        const bool has_next = (jt + 1) < NN / 64;
        if (has_next) {
            CPASYNC_B(jt + 1, cur ^ 1);
            PREFETCH((jt + 1) * 64);
        }

        // ---- MMA on current stage: warp tile 32(M) x 32(N), kt in [wk*4, wk*4+4)
        const float* Pc = Pst[cur];
        const float* Bc = Bst[cur];
#pragma unroll
        for (int k2 = 0; k2 < 4; ++k2) {
            const int kt = wk * 4 + k2;
            uint32_t a0[2], a1[2], a2[2], a3[2];
#pragma unroll
            for (int mt = 0; mt < 2; ++mt) {
                const float* pAm = &Pc[(mt * 16 + l4) * PB_STRIDE + kt * 8 + lm * 2];
                float2 lo = *(const float2*)pAm;                     // rows l4
                float2 hi = *(const float2*)(pAm + 8 * PB_STRIDE);   // rows l4+8
                a0[mt] = __float_as_uint(lo.x);
                a2[mt] = __float_as_uint(lo.y);
                a1[mt] = __float_as_uint(hi.x);
                a3[mt] = __float_as_uint(hi.y);
            }
            const float* pB = &Bc[kt * BB_KT + (wf * 32 + l4) * 8 + lm * 2];
#pragma unroll
            for (int nt = 0; nt < 4; ++nt) {
                float2 bb = *(const float2*)&pB[nt * 64];
                uint32_t b0 = __float_as_uint(bb.x);
                uint32_t b1 = __float_as_uint(bb.y);
#pragma unroll
                for (int mt = 0; mt < 2; ++mt)
                    mma_tf32(fragC[mt][nt], a0[mt], a1[mt], a2[mt], a3[mt], b0, b1);
            }
        }

        if (has_next) STORE_P(cur ^ 1);
        cp_async_wait0();
        __syncthreads();
    }

    // ---- final row-sum reduction (across c8 within each warp) ---------------
    sacc += __shfl_xor_sync(0xffffffffu, sacc, 1);
    sacc += __shfl_xor_sync(0xffffffffu, sacc, 2);
    sacc += __shfl_xor_sync(0xffffffffu, sacc, 4);
    if (c8 == 0) Ssh[ii] = sacc;

    // ---- epilogue: combine k-split partials, normalize, elu, store ----------
    float* red = smem;                        // reuse stage 0 (4 x 1024 floats)
    const int rbase = wf * 1024;
    if (wk == 1) {
#pragma unroll
        for (int mt = 0; mt < 2; ++mt)
#pragma unroll
            for (int nt = 0; nt < 4; ++nt) {
                int r = mt * 16 + l4, c = nt * 8 + lm * 2;
                red[rbase + r * 32 + c]           = fragC[mt][nt][0];
                red[rbase + r * 32 + c + 1]       = fragC[mt][nt][1];
                red[rbase + (r + 8) * 32 + c]     = fragC[mt][nt][2];
                red[rbase + (r + 8) * 32 + c + 1] = fragC[mt][nt][3];
            }
    }
    __syncthreads();
    if (wk == 0) {
#pragma unroll
        for (int mt = 0; mt < 2; ++mt) {
            const int row0 = mt * 16 + l4;
            const float s0 = 1.f / Ssh[row0];
            const float s1 = 1.f / Ssh[row0 + 8];
#pragma unroll
            for (int nt = 0; nt < 4; ++nt) {
                int r = mt * 16 + l4, c = nt * 8 + lm * 2;
                float x0 = (fragC[mt][nt][0] + red[rbase + r * 32 + c])           * s0;
                float x1 = (fragC[mt][nt][1] + red[rbase + r * 32 + c + 1])       * s0;
                float x2 = (fragC[mt][nt][2] + red[rbase + (r + 8) * 32 + c])     * s1;
                float x3 = (fragC[mt][nt][3] + red[rbase + (r + 8) * 32 + c + 1]) * s1;
                const int gcol = wf * 32 + nt * 8 + lm * 2;
                const size_t o0 = (size_t)(i0 + row0) * FOUT + gcol;
                const size_t o1 = (size_t)(i0 + row0 + 8) * FOUT + gcol;
                out[o0]     = (x0 > 0.f) ? x0 : expm1f(x0);
                out[o0 + 1] = (x1 > 0.f) ? x1 : expm1f(x1);
                out[o1]     = (x2 > 0.f) ? x2 : expm1f(x2);
                out[o1 + 1] = (x3 > 0.f) ? x3 : expm1f(x3);
            }
        }
    }
#undef PREFETCH
#undef CPASYNC_B
#undef STORE_P
}

// ---------------- launch ------------------------------------------------------
extern "C" void kernel_launch(void* const* d_in, const int* in_sizes, int n_in,
                              void* d_out, int out_size) {
    const float* h   = (const float*)d_in[0];
    const int*   adj = (const int*)d_in[1];
    const float* W   = (const float*)d_in[2];
    const float* a   = (const float*)d_in[3];
    float*       out = (float*)d_out;

    wh_kernel<<<NN / 64, 256>>>(h, W, a);

    const int smem_bytes = (2 * STAGE_FLOATS + 32) * sizeof(float);  // 84096 B
    cudaFuncSetAttribute(gat_kernel, cudaFuncAttributeMaxDynamicSharedMemorySize, smem_bytes);
    gat_kernel<<<NN / 32, 256, smem_bytes>>>(adj, out);
}

// round 9
// speedup vs baseline: 1.4662x; 1.4662x over previous
#include <cuda_runtime.h>
#include <cstdint>
#include <cstddef>

#define NN   8192
#define FIN  256
#define FOUT 128
#define ALPHA_SLOPE 0.2f

#define PB_STRIDE 72                   // P tile row stride (floats), 64 rows
#define P_FLOATS  (64 * PB_STRIDE)     // 4608 per stage

// ---------------- scratch (device globals: no allocation allowed) ------------
// g_WhB: Wh pre-staged in MMA-B fragment layout per 64-row j-tile:
//   addr = tile*8192 + kt*1024 + f*8 + (kl&3)*2 + (kl>>2),  row = tile*64+kt*8+kl
__device__ float g_WhB[(size_t)NN * FOUT];
__device__ float g_f1[NN];
__device__ float g_f2[NN];
// bitmask of adj>0: per row i, byte index = c8*128 + jt  (jt = j-tile of 64,
// c8 = 8-col chunk), packed as uint64 words: word = c8*16 + (jt>>3), byte jt&7,
// bit b = column j = jt*64 + c8*8 + b.
__device__ unsigned long long g_mask[(size_t)NN * 128];

// ---------------- helpers ----------------------------------------------------
__device__ __forceinline__ float to_tf32(float x) {
    uint32_t u;
    asm("cvt.rna.tf32.f32 %0, %1;" : "=r"(u) : "f"(x));
    return __uint_as_float(u);
}

__device__ __forceinline__ void mma_tf32(float* c,
                                         uint32_t a0, uint32_t a1, uint32_t a2, uint32_t a3,
                                         uint32_t b0, uint32_t b1) {
    asm volatile(
        "mma.sync.aligned.m16n8k8.row.col.f32.tf32.tf32.f32 "
        "{%0,%1,%2,%3}, {%4,%5,%6,%7}, {%8,%9}, {%0,%1,%2,%3};\n"
        : "+f"(c[0]), "+f"(c[1]), "+f"(c[2]), "+f"(c[3])
        : "r"(a0), "r"(a1), "r"(a2), "r"(a3), "r"(b0), "r"(b1));
}

__device__ __forceinline__ float lrelu_exp(float s) {
    s = fmaxf(s, ALPHA_SLOPE * s);
    return __expf(s);
}

// ---------------- Kernel M: adj -> bitmask -----------------------------------
// grid 8192 (one row per block), block 128. Thread (c8 = t&7, s = t>>3, 0..15)
// produces the uint64 word covering tiles jt = s*8 .. s*8+7 for column chunk c8.
__global__ void __launch_bounds__(128) mask_kernel(const int* __restrict__ adj) {
    const int i  = blockIdx.x;
    const int t  = threadIdx.x;
    const int c8 = t & 7;
    const int s  = t >> 3;

    const int* row = adj + (size_t)i * NN;
    unsigned long long w = 0;
#pragma unroll
    for (int k = 0; k < 8; ++k) {
        const int j = (s * 8 + k) * 64 + c8 * 8;
        int4 a = *(const int4*)(row + j);
        int4 b = *(const int4*)(row + j + 4);
        unsigned byte = 0;
        byte |= (a.x > 0) ? 1u   : 0u;
        byte |= (a.y > 0) ? 2u   : 0u;
        byte |= (a.z > 0) ? 4u   : 0u;
        byte |= (a.w > 0) ? 8u   : 0u;
        byte |= (b.x > 0) ? 16u  : 0u;
        byte |= (b.y > 0) ? 32u  : 0u;
        byte |= (b.z > 0) ? 64u  : 0u;
        byte |= (b.w > 0) ? 128u : 0u;
        w |= (unsigned long long)byte << (k * 8);
    }
    g_mask[(size_t)i * 128 + c8 * 16 + s] = w;
}

// ---------------- Kernel A: Wh = h@W (stored in B layout), f1, f2 ------------
__global__ void __launch_bounds__(256) wh_kernel(const float* __restrict__ h,
                                                 const float* __restrict__ W,
                                                 const float* __restrict__ a) {
    __shared__ float hs[64][64];
    __shared__ float Ws[64][FOUT];

    const int t  = threadIdx.x;
    const int i0 = blockIdx.x * 64;
    const int tf = t & 31;      // 4 output cols tf*4..+3
    const int ti = t >> 5;      // 8 output rows ti*8..+7  (kt = ti, kl = r)

    float acc[8][4];
#pragma unroll
    for (int r = 0; r < 8; ++r)
#pragma unroll
        for (int c = 0; c < 4; ++c) acc[r][c] = 0.f;

    for (int kc = 0; kc < 4; ++kc) {
        __syncthreads();
#pragma unroll
        for (int idx = t; idx < 1024; idx += 256) {
            int row = idx >> 4, c = idx & 15;
            *(float4*)&hs[row][c * 4] =
                *(const float4*)&h[(size_t)(i0 + row) * FIN + kc * 64 + c * 4];
        }
#pragma unroll
        for (int idx = t; idx < 2048; idx += 256) {
            int row = idx >> 5, c = idx & 31;
            *(float4*)&Ws[row][c * 4] =
                *(const float4*)&W[(size_t)(kc * 64 + row) * FOUT + c * 4];
        }
        __syncthreads();
#pragma unroll 8
        for (int k = 0; k < 64; ++k) {
            float4 wv = *(float4*)&Ws[k][tf * 4];
#pragma unroll
            for (int r = 0; r < 8; ++r) {
                float hv = hs[ti * 8 + r][k];
                acc[r][0] += hv * wv.x;
                acc[r][1] += hv * wv.y;
                acc[r][2] += hv * wv.z;
                acc[r][3] += hv * wv.w;
            }
        }
    }

    float4 a1v = *(const float4*)&a[tf * 4];
    float4 a2v = *(const float4*)&a[FOUT + tf * 4];
#pragma unroll
    for (int r = 0; r < 8; ++r) {
        float v1 = acc[r][0] * a1v.x + acc[r][1] * a1v.y + acc[r][2] * a1v.z + acc[r][3] * a1v.w;
        float v2 = acc[r][0] * a2v.x + acc[r][1] * a2v.y + acc[r][2] * a2v.z + acc[r][3] * a2v.w;
#pragma unroll
        for (int off = 16; off > 0; off >>= 1) {
            v1 += __shfl_xor_sync(0xffffffffu, v1, off);
            v2 += __shfl_xor_sync(0xffffffffu, v2, off);
        }
        if (tf == 0) {
            g_f1[i0 + ti * 8 + r] = v1;
            g_f2[i0 + ti * 8 + r] = v2;
        }
    }

    // store into B-staged layout: slot (kl&3)*2 + (kl>>2); rows r and r+4 pair
    float* base = &g_WhB[(size_t)blockIdx.x * 8192 + ti * 1024];
#pragma unroll
    for (int r = 0; r < 4; ++r) {
#pragma unroll
        for (int c = 0; c < 4; ++c) {
            float2 v;
            v.x = to_tf32(acc[r][c]);       // kl = r     -> slot 2r
            v.y = to_tf32(acc[r + 4][c]);   // kl = r + 4 -> slot 2r+1
            *(float2*)&base[(tf * 4 + c) * 8 + r * 2] = v;
        }
    }
}

// ---------------- Kernel C: fused masked-softmax attention -------------------
// grid 128, block 512 (16 warps). Block tile 64(i) x 128(f), j-tiles of 64.
// Warp grid: wf(N,8) x wk(K,2); warp tile 64(M) x 16(N), k-split 2.
// B fragments loaded straight from L2 (g_WhB) via coalesced LDG.64 — no smem B.
// P double-buffered in smem, column-permuted so A-fragments are LDS.64.
__global__ void __launch_bounds__(512, 1) gat_kernel(float* __restrict__ out) {
    extern __shared__ float smem[];
    float* Pst[2];
    Pst[0] = smem;
    Pst[1] = smem + P_FLOATS;
    float* Ssh = smem + 2 * P_FLOATS;   // 64 floats
    float* red = smem;                  // epilogue overlay (8192 <= 9216)

    const int t    = threadIdx.x;
    const int lane = t & 31;
    const int wid  = t >> 5;
    const int i0   = blockIdx.x * 64;

    const int ii = t >> 3;            // P producer row (0..63)
    const int c8 = t & 7;             // P producer 8-col chunk

    const int wf = wid >> 1;          // 0..7 (N: 16 cols)
    const int wk = wid & 1;           // 0..1 (K split)
    const int l4 = lane >> 2;
    const int lm = lane & 3;

    const float f1i = g_f1[i0 + ii];
    float sacc = 0.f;

    float fragC[4][2][4];
#pragma unroll
    for (int mt = 0; mt < 4; ++mt)
#pragma unroll
        for (int nt = 0; nt < 2; ++nt)
#pragma unroll
            for (int c = 0; c < 4; ++c) fragC[mt][nt][c] = 0.f;

    // invariant addresses
    const unsigned long long* mrow = g_mask + (size_t)(i0 + ii) * 128 + c8 * 16;
    const float* bwarp = g_WhB + (wf * 16 + l4) * 8 + lm * 2;   // + jt*8192 + kt*1024 + nt*64
    float* pdst[2];
    pdst[0] = &Pst[0][ii * PB_STRIDE + c8 * 8];
    pdst[1] = &Pst[1][ii * PB_STRIDE + c8 * 8];

    unsigned long long mw = mrow[0];
    unsigned mb;
    float4 f2a, f2b;

#define PREFETCH_F2(J0)                                        \
    do {                                                       \
        f2a = *(const float4*)&g_f2[(J0) + c8 * 8];            \
        f2b = *(const float4*)&g_f2[(J0) + c8 * 8 + 4];        \
    } while (0)

// P written permuted: col q (0..7) -> slot (q&3)*2 + (q>>2)
// slots = [c0,c4,c1,c5,c2,c6,c3,c7]; A-frag (col lm, lm+4) is one float2.
#define STORE_P(ST)                                                         \
    do {                                                                    \
        float4 pva, pvb;                                                    \
        pva.x = (mb & 1u)    ? to_tf32(lrelu_exp(f1i + f2a.x)) : 0.f;       \
        pva.y = (mb & 2u)    ? to_tf32(lrelu_exp(f1i + f2a.y)) : 0.f;       \
        pva.z = (mb & 4u)    ? to_tf32(lrelu_exp(f1i + f2a.z)) : 0.f;       \
        pva.w = (mb & 8u)    ? to_tf32(lrelu_exp(f1i + f2a.w)) : 0.f;       \
        pvb.x = (mb & 16u)   ? to_tf32(lrelu_exp(f1i + f2b.x)) : 0.f;       \
        pvb.y = (mb & 32u)   ? to_tf32(lrelu_exp(f1i + f2b.y)) : 0.f;       \
        pvb.z = (mb & 64u)   ? to_tf32(lrelu_exp(f1i + f2b.z)) : 0.f;       \
        pvb.w = (mb & 128u)  ? to_tf32(lrelu_exp(f1i + f2b.w)) : 0.f;       \
        float4 q0 = make_float4(pva.x, pvb.x, pva.y, pvb.y);                \
        float4 q1 = make_float4(pva.z, pvb.z, pva.w, pvb.w);                \
        *(float4*)(pdst[ST])     = q0;                                      \
        *(float4*)(pdst[ST] + 4) = q1;                                      \
        sacc += pva.x + pva.y + pva.z + pva.w                               \
              + pvb.x + pvb.y + pvb.z + pvb.w;                              \
    } while (0)

    // prologue: build P for tile 0
    PREFETCH_F2(0);
    mb = (unsigned)(mw & 0xffull);
    STORE_P(0);
    __syncthreads();

#pragma unroll 1
    for (int jt = 0; jt < NN / 64; ++jt) {
        const int cur = jt & 1;
        const bool has_next = (jt + 1) < NN / 64;
        if (has_next) {
            const int jn = jt + 1;
            if ((jn & 7) == 0) mw = mrow[jn >> 3];
            mb = (unsigned)((mw >> ((jn & 7) * 8)) & 0xffull);
            PREFETCH_F2(jn * 64);
        }

        // ---- B fragments for this tile straight from L2 (8 x LDG.64) -------
        const float* bt = bwarp + (size_t)jt * 8192 + wk * 4 * 1024;
        float2 bb[4][2];
#pragma unroll
        for (int k2 = 0; k2 < 4; ++k2)
#pragma unroll
            for (int nt = 0; nt < 2; ++nt)
                bb[k2][nt] = *(const float2*)(bt + k2 * 1024 + nt * 64);

        // ---- A fragments from smem + MMA -----------------------------------
        const float* Pc = Pst[cur];
        const float* abase = &Pc[l4 * PB_STRIDE + wk * 32 + lm * 2];
#pragma unroll
        for (int k2 = 0; k2 < 4; ++k2) {
            uint32_t a0[4], a1[4], a2[4], a3[4];
#pragma unroll
            for (int mt = 0; mt < 4; ++mt) {
                const float* pAm = abase + mt * 16 * PB_STRIDE + k2 * 8;
                float2 lo = *(const float2*)pAm;                     // row mt*16+l4
                float2 hi = *(const float2*)(pAm + 8 * PB_STRIDE);   // row +8
                a0[mt] = __float_as_uint(lo.x);
                a2[mt] = __float_as_uint(lo.y);
                a1[mt] = __float_as_uint(hi.x);
                a3[mt] = __float_as_uint(hi.y);
            }
#pragma unroll
            for (int nt = 0; nt < 2; ++nt) {
                uint32_t b0 = __float_as_uint(bb[k2][nt].x);
                uint32_t b1 = __float_as_uint(bb[k2][nt].y);
#pragma unroll
                for (int mt = 0; mt < 4; ++mt)
                    mma_tf32(fragC[mt][nt], a0[mt], a1[mt], a2[mt], a3[mt], b0, b1);
            }
        }

        if (has_next) STORE_P(cur ^ 1);
        __syncthreads();
    }

    // ---- final row-sum reduction (across c8 within each warp) ---------------
    sacc += __shfl_xor_sync(0xffffffffu, sacc, 1);
    sacc += __shfl_xor_sync(0xffffffffu, sacc, 2);
    sacc += __shfl_xor_sync(0xffffffffu, sacc, 4);
    if (c8 == 0) Ssh[ii] = sacc;
    __syncthreads();

    // ---- epilogue: combine k-split partials, normalize, elu, store ----------
    const int rbase = wf * 1024;      // 64 rows x 16 cols per wf
    if (wk == 1) {
#pragma unroll
        for (int mt = 0; mt < 4; ++mt)
#pragma unroll
            for (int nt = 0; nt < 2; ++nt) {
                int r = mt * 16 + l4, c = nt * 8 + lm * 2;
                red[rbase + r * 16 + c]           = fragC[mt][nt][0];
                red[rbase + r * 16 + c + 1]       = fragC[mt][nt][1];
                red[rbase + (r + 8) * 16 + c]     = fragC[mt][nt][2];
                red[rbase + (r + 8) * 16 + c + 1] = fragC[mt][nt][3];
            }
    }
    __syncthreads();
    if (wk == 0) {
#pragma unroll
        for (int mt = 0; mt < 4; ++mt) {
            const int row0 = mt * 16 + l4;
            const float s0 = 1.f / Ssh[row0];
            const float s1 = 1.f / Ssh[row0 + 8];
#pragma unroll
            for (int nt = 0; nt < 2; ++nt) {
                int r = mt * 16 + l4, c = nt * 8 + lm * 2;
                float x0 = (fragC[mt][nt][0] + red[rbase + r * 16 + c])           * s0;
                float x1 = (fragC[mt][nt][1] + red[rbase + r * 16 + c + 1])       * s0;
                float x2 = (fragC[mt][nt][2] + red[rbase + (r + 8) * 16 + c])     * s1;
                float x3 = (fragC[mt][nt][3] + red[rbase + (r + 8) * 16 + c + 1]) * s1;
                const int gcol = wf * 16 + nt * 8 + lm * 2;
                const size_t o0 = (size_t)(i0 + row0) * FOUT + gcol;
                const size_t o1 = (size_t)(i0 + row0 + 8) * FOUT + gcol;
                out[o0]     = (x0 > 0.f) ? x0 : expm1f(x0);
                out[o0 + 1] = (x1 > 0.f) ? x1 : expm1f(x1);
                out[o1]     = (x2 > 0.f) ? x2 : expm1f(x2);
                out[o1 + 1] = (x3 > 0.f) ? x3 : expm1f(x3);
            }
        }
    }
#undef PREFETCH_F2
#undef STORE_P
}

// ---------------- launch ------------------------------------------------------
extern "C" void kernel_launch(void* const* d_in, const int* in_sizes, int n_in,
                              void* d_out, int out_size) {
    const float* h   = (const float*)d_in[0];
    const int*   adj = (const int*)d_in[1];
    const float* W   = (const float*)d_in[2];
    const float* a   = (const float*)d_in[3];
    float*       out = (float*)d_out;

    mask_kernel<<<NN, 128>>>(adj);
    wh_kernel<<<NN / 64, 256>>>(h, W, a);

    const int smem_bytes = (2 * P_FLOATS + 64) * sizeof(float);  // 37120 B
    cudaFuncSetAttribute(gat_kernel, cudaFuncAttributeMaxDynamicSharedMemorySize, smem_bytes);
    gat_kernel<<<NN / 64, 512, smem_bytes>>>(out);
}